// round 1
// baseline (speedup 1.0000x reference)
#include <cuda_runtime.h>
#include <cuda_bf16.h>

#define N_NODES 50000
#define N_EDGES 800000
#define D 64            // D_IN == D_OUT == 64
#define D4 16           // D/4 float4 per row

// Scratch: neighbor accumulator [N_NODES, D] (device global — no allocs allowed)
__device__ float g_neighbor[N_NODES * D];

// ---------------------------------------------------------------------------
// Kernel 1: zero the neighbor accumulator (12.8 MB, float4 stores)
// ---------------------------------------------------------------------------
__global__ void zero_kernel() {
    int i = blockIdx.x * blockDim.x + threadIdx.x;   // over N_NODES*D4 float4
    if (i < N_NODES * D4) {
        reinterpret_cast<float4*>(g_neighbor)[i] = make_float4(0.f, 0.f, 0.f, 0.f);
    }
}

// ---------------------------------------------------------------------------
// Kernel 2: edge scatter.  16 threads per edge, each handles one float4 chunk.
//   gathered = features[src] * w ;  neighbor[dst] += gathered  (vector RED)
// ---------------------------------------------------------------------------
__global__ void scatter_kernel(const float4* __restrict__ feat4,
                               const int*    __restrict__ esrc,
                               const int*    __restrict__ edst,
                               const float*  __restrict__ ew) {
    int t = blockIdx.x * blockDim.x + threadIdx.x;
    int e = t >> 4;
    int c = t & 15;
    if (e >= N_EDGES) return;

    int   s = __ldg(esrc + e);
    int   d = __ldg(edst + e);
    float w = __ldg(ew + e);

    float4 f = __ldg(feat4 + (size_t)s * D4 + c);

    float4* p = reinterpret_cast<float4*>(g_neighbor) + (size_t)d * D4 + c;
    asm volatile("red.global.add.v4.f32 [%0], {%1, %2, %3, %4};"
                 :: "l"(p), "f"(f.x * w), "f"(f.y * w), "f"(f.z * w), "f"(f.w * w)
                 : "memory");
}

// ---------------------------------------------------------------------------
// Kernel 3: per-node GEMM + bias + L2 normalize.
//   out[i,:] = normalize( [features[i], neighbor[i]] @ W^T + b )
// Block = 128 threads = 8 node-slots x 16 output-quads.
// W (64x128) is transposed into smem as Wt[k][o] (k-major, conflict-free).
// ---------------------------------------------------------------------------
__global__ void gemm_norm_kernel(const float4* __restrict__ feat4,
                                 const float*  __restrict__ W,
                                 const float*  __restrict__ bias,
                                 float4*       __restrict__ out4) {
    __shared__ float4 Wt[128 * D4];   // Wt[k][q] : 128 k-rows of 16 float4 (32 KB)
    __shared__ float4 bias4[D4];
    __shared__ float  xs[8][128];     // combined row per node-slot

    int t = threadIdx.x;

    // Load + transpose W: W[o][k] (row-major 64x128) -> Wt_flat[k*64 + o]
    float* Wt_f = reinterpret_cast<float*>(Wt);
    for (int i = t; i < D * 2 * D; i += blockDim.x) {
        int o = i >> 7;        // 0..63
        int k = i & 127;       // 0..127
        Wt_f[k * D + o] = __ldg(W + i);
    }
    if (t < D4) bias4[t] = reinterpret_cast<const float4*>(bias)[t];
    __syncthreads();

    int slot = t >> 4;   // 0..7  (node within block)
    int q    = t & 15;   // 0..15 (output float4 index)

    const float4* neigh4 = reinterpret_cast<const float4*>(g_neighbor);

    for (int node = blockIdx.x * 8 + slot; node < N_NODES; node += gridDim.x * 8) {
        // Stage combined = [features[node], neighbor[node]] into smem (128 floats)
        float4 f  = __ldg(feat4 + (size_t)node * D4 + q);
        float4 nb = neigh4[(size_t)node * D4 + q];
        reinterpret_cast<float4*>(xs[slot])[q]      = f;
        reinterpret_cast<float4*>(xs[slot])[D4 + q] = nb;
        __syncwarp();

        float4 acc = bias4[q];
        const float4* xv = reinterpret_cast<const float4*>(xs[slot]);
#pragma unroll 8
        for (int k4 = 0; k4 < 32; k4++) {
            float4 x4 = xv[k4];
            float4 w0 = Wt[(k4 * 4 + 0) * D4 + q];
            float4 w1 = Wt[(k4 * 4 + 1) * D4 + q];
            float4 w2 = Wt[(k4 * 4 + 2) * D4 + q];
            float4 w3 = Wt[(k4 * 4 + 3) * D4 + q];
            acc.x += x4.x * w0.x; acc.y += x4.x * w0.y; acc.z += x4.x * w0.z; acc.w += x4.x * w0.w;
            acc.x += x4.y * w1.x; acc.y += x4.y * w1.y; acc.z += x4.y * w1.z; acc.w += x4.y * w1.w;
            acc.x += x4.z * w2.x; acc.y += x4.z * w2.y; acc.z += x4.z * w2.z; acc.w += x4.z * w2.w;
            acc.x += x4.w * w3.x; acc.y += x4.w * w3.y; acc.z += x4.w * w3.z; acc.w += x4.w * w3.w;
        }

        // L2 norm across the 64 outputs of this node (16 lanes x 4 each)
        float ss = acc.x * acc.x + acc.y * acc.y + acc.z * acc.z + acc.w * acc.w;
        ss += __shfl_xor_sync(0xffffffffu, ss, 8);
        ss += __shfl_xor_sync(0xffffffffu, ss, 4);
        ss += __shfl_xor_sync(0xffffffffu, ss, 2);
        ss += __shfl_xor_sync(0xffffffffu, ss, 1);
        float inv = 1.0f / fmaxf(sqrtf(ss), 1e-12f);

        acc.x *= inv; acc.y *= inv; acc.z *= inv; acc.w *= inv;
        out4[(size_t)node * D4 + q] = acc;
        __syncwarp();   // protect xs before next iteration's overwrite
    }
}

// ---------------------------------------------------------------------------
// Launch: inputs in metadata order:
//   0: features [50000,64] f32   1: edge_src [800000] i32
//   2: edge_dst [800000] i32     3: edge_weight [800000] f32
//   4: W [64,128] f32            5: b [64] f32
// Output: [50000,64] f32
// ---------------------------------------------------------------------------
extern "C" void kernel_launch(void* const* d_in, const int* in_sizes, int n_in,
                              void* d_out, int out_size) {
    const float4* feat4 = (const float4*)d_in[0];
    const int*    esrc  = (const int*)d_in[1];
    const int*    edst  = (const int*)d_in[2];
    const float*  ew    = (const float*)d_in[3];
    const float*  W     = (const float*)d_in[4];
    const float*  bias  = (const float*)d_in[5];
    float4*       out4  = (float4*)d_out;

    // 1. zero neighbor accumulator
    {
        int n = N_NODES * D4;
        zero_kernel<<<(n + 255) / 256, 256>>>();
    }
    // 2. edge scatter (16 threads/edge)
    {
        long long total = (long long)N_EDGES * 16;
        int blocks = (int)((total + 255) / 256);
        scatter_kernel<<<blocks, 256>>>(feat4, esrc, edst, ew);
    }
    // 3. gemm + bias + normalize
    {
        int blocks = N_NODES / 8;   // 6250, exact
        gemm_norm_kernel<<<blocks, 128>>>(feat4, W, bias, out4);
    }
    (void)in_sizes; (void)n_in; (void)out_size;
}

// round 2
// speedup vs baseline: 1.6812x; 1.6812x over previous
#include <cuda_runtime.h>
#include <cuda_bf16.h>

#define N_NODES 50000
#define N_EDGES 800000
#define D 64
#define D4 16

// ---------------- scratch (device globals; no allocs allowed) ----------------
__device__ int   g_deg[N_NODES];
__device__ int   g_cur[N_NODES];
__device__ int   g_start[N_NODES + 1];
__device__ int2  g_edges[N_EDGES];          // (src, weight-as-int) sorted by dst
__device__ float g_neighbor[N_NODES * D];

// ---------------------------------------------------------------------------
// K1: zero degree counters
// ---------------------------------------------------------------------------
__global__ void zero_deg_kernel() {
    int i = blockIdx.x * blockDim.x + threadIdx.x;
    if (i < N_NODES) g_deg[i] = 0;
}

// ---------------------------------------------------------------------------
// K2: histogram of edge destinations
// ---------------------------------------------------------------------------
__global__ void hist_kernel(const int* __restrict__ edst) {
    int e = blockIdx.x * blockDim.x + threadIdx.x;
    if (e < N_EDGES) atomicAdd(&g_deg[edst[e]], 1);
}

// ---------------------------------------------------------------------------
// K3: exclusive scan of degrees -> g_start / g_cur. One block, 1024 threads,
// each thread owns 49 contiguous nodes (1024*49 = 50176 >= 50000).
// ---------------------------------------------------------------------------
__global__ void scan_kernel() {
    __shared__ int ssum[1024];
    const int CH = 49;
    int t = threadIdx.x;
    int base = t * CH;

    int s = 0;
    for (int j = 0; j < CH; j++) {
        int i = base + j;
        if (i < N_NODES) s += g_deg[i];
    }
    ssum[t] = s;
    __syncthreads();
    // Hillis-Steele inclusive scan
    for (int off = 1; off < 1024; off <<= 1) {
        int v = (t >= off) ? ssum[t - off] : 0;
        __syncthreads();
        ssum[t] += v;
        __syncthreads();
    }
    int run = ssum[t] - s;   // exclusive prefix for this thread's chunk
    for (int j = 0; j < CH; j++) {
        int i = base + j;
        if (i < N_NODES) {
            int d = g_deg[i];
            g_start[i] = run;
            g_cur[i]   = run;
            run += d;
        }
    }
    if (t == 0) g_start[N_NODES] = N_EDGES;
}

// ---------------------------------------------------------------------------
// K4: scatter edge records into CSR slots (one 8B write per edge)
// ---------------------------------------------------------------------------
__global__ void fill_kernel(const int* __restrict__ esrc,
                            const int* __restrict__ edst,
                            const float* __restrict__ ew) {
    int e = blockIdx.x * blockDim.x + threadIdx.x;
    if (e < N_EDGES) {
        int d = edst[e];
        int p = atomicAdd(&g_cur[d], 1);
        g_edges[p] = make_int2(__ldg(esrc + e), __float_as_int(__ldg(ew + e)));
    }
}

// ---------------------------------------------------------------------------
// K5: gather-accumulate. 16 lanes per node; lane c owns float4 chunk c.
// Edge record load is an 8B broadcast; feature-row load is coalesced 256B.
// No float atomics; output write initializes g_neighbor (no pre-zero needed).
// ---------------------------------------------------------------------------
__global__ void gather_kernel(const float4* __restrict__ feat4) {
    int t = blockIdx.x * blockDim.x + threadIdx.x;
    int n = t >> 4;
    int c = t & 15;
    if (n >= N_NODES) return;

    int j0 = g_start[n];
    int j1 = g_start[n + 1];
    float4 acc = make_float4(0.f, 0.f, 0.f, 0.f);
    for (int j = j0; j < j1; j++) {
        int2  r = __ldg(&g_edges[j]);
        float w = __int_as_float(r.y);
        float4 f = __ldg(feat4 + (size_t)r.x * D4 + c);
        acc.x += w * f.x;
        acc.y += w * f.y;
        acc.z += w * f.z;
        acc.w += w * f.w;
    }
    reinterpret_cast<float4*>(g_neighbor)[(size_t)n * D4 + c] = acc;
}

// ---------------------------------------------------------------------------
// K6: register-tiled GEMM + bias + L2 normalize.
//   out[n,:] = normalize([feat[n], neigh[n]] @ W^T + b)
// Block: 256 threads, 128-node tile. Thread (tx=t&7, ty=t>>3) computes
// 4 nodes (4*ty..) x 8 outs (cols 4tx..4tx+3 and 32+4tx..32+4tx+3).
// W in smem once per block (pitch 68 -> conflict-free float4 reads),
// x in smem (pitch 130 -> conflict-free broadcast scalar reads).
// ---------------------------------------------------------------------------
#define XP 130
#define WP 68
#define GEMM_SMEM ((128 * XP + 128 * WP) * 4)

__global__ __launch_bounds__(256, 2)
void gemm_norm_kernel(const float4* __restrict__ feat4,
                      const float*  __restrict__ W,
                      const float*  __restrict__ bias,
                      float4*       __restrict__ out4) {
    extern __shared__ float sm[];
    float* xs = sm;              // [128 nodes][XP]
    float* ws = sm + 128 * XP;   // [128 k][WP]

    int t = threadIdx.x;
    int node0 = blockIdx.x * 128;
    const float4* neigh4 = reinterpret_cast<const float4*>(g_neighbor);

    // W[o][k] (64x128 row-major) -> ws[k][o]
    for (int i = t; i < 64 * 128; i += 256) {
        int o = i >> 7, k = i & 127;
        ws[k * WP + o] = __ldg(W + i);
    }
    // x = [feat | neigh], 128 nodes x 32 float4
    for (int idx = t; idx < 128 * 32; idx += 256) {
        int n = idx >> 5, q = idx & 31;
        int node = node0 + n;
        float4 v = make_float4(0.f, 0.f, 0.f, 0.f);
        if (node < N_NODES)
            v = (q < 16) ? __ldg(feat4 + (size_t)node * 16 + q)
                         : neigh4[(size_t)node * 16 + (q - 16)];
        float* xr = xs + n * XP + q * 4;
        xr[0] = v.x; xr[1] = v.y; xr[2] = v.z; xr[3] = v.w;
    }
    __syncthreads();

    int tx = t & 7;
    int ty = t >> 3;

    float acc[4][8];
#pragma unroll
    for (int j = 0; j < 4; j++) {
        float bA = __ldg(bias + 4 * tx + j);
        float bB = __ldg(bias + 32 + 4 * tx + j);
#pragma unroll
        for (int i = 0; i < 4; i++) { acc[i][j] = bA; acc[i][4 + j] = bB; }
    }

#pragma unroll 4
    for (int k = 0; k < 128; k++) {
        float4 wA = *reinterpret_cast<const float4*>(ws + k * WP + 4 * tx);
        float4 wB = *reinterpret_cast<const float4*>(ws + k * WP + 32 + 4 * tx);
#pragma unroll
        for (int i = 0; i < 4; i++) {
            float x = xs[(ty * 4 + i) * XP + k];
            acc[i][0] += x * wA.x; acc[i][1] += x * wA.y;
            acc[i][2] += x * wA.z; acc[i][3] += x * wA.w;
            acc[i][4] += x * wB.x; acc[i][5] += x * wB.y;
            acc[i][6] += x * wB.z; acc[i][7] += x * wB.w;
        }
    }

    // per-node L2 norm: reduce sum of squares over the 8 tx lanes (same warp)
#pragma unroll
    for (int i = 0; i < 4; i++) {
        float ss = 0.f;
#pragma unroll
        for (int j = 0; j < 8; j++) ss += acc[i][j] * acc[i][j];
        ss += __shfl_xor_sync(0xffffffffu, ss, 1);
        ss += __shfl_xor_sync(0xffffffffu, ss, 2);
        ss += __shfl_xor_sync(0xffffffffu, ss, 4);
        float inv = 1.0f / fmaxf(sqrtf(ss), 1e-12f);

        int node = node0 + ty * 4 + i;
        if (node < N_NODES) {
            float4 oA = make_float4(acc[i][0] * inv, acc[i][1] * inv,
                                    acc[i][2] * inv, acc[i][3] * inv);
            float4 oB = make_float4(acc[i][4] * inv, acc[i][5] * inv,
                                    acc[i][6] * inv, acc[i][7] * inv);
            out4[(size_t)node * 16 + tx]     = oA;
            out4[(size_t)node * 16 + 8 + tx] = oB;
        }
    }
}

// ---------------------------------------------------------------------------
// inputs: 0 features[50000,64] f32  1 edge_src[800000] i32  2 edge_dst i32
//         3 edge_weight f32         4 W[64,128] f32         5 b[64] f32
// ---------------------------------------------------------------------------
extern "C" void kernel_launch(void* const* d_in, const int* in_sizes, int n_in,
                              void* d_out, int out_size) {
    const float4* feat4 = (const float4*)d_in[0];
    const int*    esrc  = (const int*)d_in[1];
    const int*    edst  = (const int*)d_in[2];
    const float*  ew    = (const float*)d_in[3];
    const float*  W     = (const float*)d_in[4];
    const float*  bias  = (const float*)d_in[5];
    float4*       out4  = (float4*)d_out;

    cudaFuncSetAttribute(gemm_norm_kernel,
                         cudaFuncAttributeMaxDynamicSharedMemorySize, GEMM_SMEM);

    zero_deg_kernel<<<(N_NODES + 255) / 256, 256>>>();
    hist_kernel<<<(N_EDGES + 255) / 256, 256>>>(edst);
    scan_kernel<<<1, 1024>>>();
    fill_kernel<<<(N_EDGES + 255) / 256, 256>>>(esrc, edst, ew);
    {
        long long total = (long long)N_NODES * 16;
        gather_kernel<<<(int)((total + 255) / 256), 256>>>(feat4);
    }
    gemm_norm_kernel<<<(N_NODES + 127) / 128, 256, GEMM_SMEM>>>(feat4, W, bias, out4);

    (void)in_sizes; (void)n_in; (void)out_size;
}

// round 3
// speedup vs baseline: 3.0682x; 1.8250x over previous
#include <cuda_runtime.h>
#include <cuda_bf16.h>

#define N_NODES 50000
#define N_EDGES 800000
#define D 64
#define D4 16

// ---------------- scratch (device globals; no allocs allowed) ----------------
__device__ int   g_deg[N_NODES];
__device__ int   g_cur[N_NODES];
__device__ int   g_start[N_NODES + 1];
__device__ int   g_bsum[256];
__device__ int2  g_edges[N_EDGES];          // (src, weight-as-int) grouped by dst
__device__ float g_neighbor[N_NODES * D];

// ---------------------------------------------------------------------------
// K1: zero degree counters
// ---------------------------------------------------------------------------
__global__ void zero_deg_kernel() {
    int i = blockIdx.x * blockDim.x + threadIdx.x;
    if (i < N_NODES) g_deg[i] = 0;
}

// ---------------------------------------------------------------------------
// K2: histogram of edge destinations (4 edges/thread, int4 loads)
// ---------------------------------------------------------------------------
__global__ void hist_kernel(const int4* __restrict__ edst4) {
    int i = blockIdx.x * blockDim.x + threadIdx.x;
    if (i < N_EDGES / 4) {
        int4 d = __ldg(edst4 + i);
        atomicAdd(&g_deg[d.x], 1);
        atomicAdd(&g_deg[d.y], 1);
        atomicAdd(&g_deg[d.z], 1);
        atomicAdd(&g_deg[d.w], 1);
    }
}

// ---------------------------------------------------------------------------
// K3a/b/c: two-level exclusive scan of degrees -> g_start / g_cur
// ---------------------------------------------------------------------------
__device__ __forceinline__ int block_incl_scan_256(int v, int t, int* warp_sums) {
    int x = v;
#pragma unroll
    for (int off = 1; off < 32; off <<= 1) {
        int y = __shfl_up_sync(0xffffffffu, x, off);
        if ((t & 31) >= off) x += y;
    }
    if ((t & 31) == 31) warp_sums[t >> 5] = x;
    __syncthreads();
    if (t < 8) {
        int s = warp_sums[t];
#pragma unroll
        for (int off = 1; off < 8; off <<= 1) {
            int y = __shfl_up_sync(0x000000ffu, s, off);
            if (t >= off) s += y;
        }
        warp_sums[t] = s;
    }
    __syncthreads();
    if (t >= 32) x += warp_sums[(t >> 5) - 1];
    return x;
}

__global__ void scan1_kernel() {          // 196 blocks x 256
    __shared__ int warp_sums[8];
    int t = threadIdx.x;
    int i = blockIdx.x * 256 + t;
    int v = (i < N_NODES) ? g_deg[i] : 0;
    int incl = block_incl_scan_256(v, t, warp_sums);
    if (i < N_NODES) g_start[i] = incl - v;          // block-local exclusive
    if (t == 255) g_bsum[blockIdx.x] = incl;         // block total
}

__global__ void scan2_kernel() {          // 1 block x 256
    __shared__ int warp_sums[8];
    int t = threadIdx.x;
    int v = (t < 196) ? g_bsum[t] : 0;
    int incl = block_incl_scan_256(v, t, warp_sums);
    if (t < 196) g_bsum[t] = incl - v;               // exclusive block offset
}

__global__ void scan3_kernel() {          // 196 blocks x 256
    int i = blockIdx.x * 256 + threadIdx.x;
    if (i < N_NODES) {
        int s = g_start[i] + g_bsum[blockIdx.x];
        g_start[i] = s;
        g_cur[i]   = s;
    }
    if (i == 0) g_start[N_NODES] = N_EDGES;
}

// ---------------------------------------------------------------------------
// K4: scatter edge records into CSR slots (4 edges/thread, int4 loads)
// ---------------------------------------------------------------------------
__global__ void fill_kernel(const int4*   __restrict__ esrc4,
                            const int4*   __restrict__ edst4,
                            const float4* __restrict__ ew4) {
    int i = blockIdx.x * blockDim.x + threadIdx.x;
    if (i >= N_EDGES / 4) return;
    int4   s = __ldg(esrc4 + i);
    int4   d = __ldg(edst4 + i);
    float4 w = __ldg(ew4 + i);
    int p0 = atomicAdd(&g_cur[d.x], 1);
    int p1 = atomicAdd(&g_cur[d.y], 1);
    int p2 = atomicAdd(&g_cur[d.z], 1);
    int p3 = atomicAdd(&g_cur[d.w], 1);
    g_edges[p0] = make_int2(s.x, __float_as_int(w.x));
    g_edges[p1] = make_int2(s.y, __float_as_int(w.y));
    g_edges[p2] = make_int2(s.z, __float_as_int(w.z));
    g_edges[p3] = make_int2(s.w, __float_as_int(w.w));
}

// ---------------------------------------------------------------------------
// K5: gather-accumulate, 16 lanes/node, unrolled x4 for MLP.
// ---------------------------------------------------------------------------
__global__ void gather_kernel(const float4* __restrict__ feat4) {
    int t = blockIdx.x * blockDim.x + threadIdx.x;
    int n = t >> 4;
    int c = t & 15;
    if (n >= N_NODES) return;

    int j0 = g_start[n];
    int j1 = g_start[n + 1];
    float4 acc = make_float4(0.f, 0.f, 0.f, 0.f);

    int j = j0;
    for (; j + 4 <= j1; j += 4) {
        int2 r0 = __ldg(&g_edges[j + 0]);
        int2 r1 = __ldg(&g_edges[j + 1]);
        int2 r2 = __ldg(&g_edges[j + 2]);
        int2 r3 = __ldg(&g_edges[j + 3]);
        float4 f0 = __ldg(feat4 + (size_t)r0.x * D4 + c);
        float4 f1 = __ldg(feat4 + (size_t)r1.x * D4 + c);
        float4 f2 = __ldg(feat4 + (size_t)r2.x * D4 + c);
        float4 f3 = __ldg(feat4 + (size_t)r3.x * D4 + c);
        float w0 = __int_as_float(r0.y), w1 = __int_as_float(r1.y);
        float w2 = __int_as_float(r2.y), w3 = __int_as_float(r3.y);
        acc.x += w0 * f0.x; acc.y += w0 * f0.y; acc.z += w0 * f0.z; acc.w += w0 * f0.w;
        acc.x += w1 * f1.x; acc.y += w1 * f1.y; acc.z += w1 * f1.z; acc.w += w1 * f1.w;
        acc.x += w2 * f2.x; acc.y += w2 * f2.y; acc.z += w2 * f2.z; acc.w += w2 * f2.w;
        acc.x += w3 * f3.x; acc.y += w3 * f3.y; acc.z += w3 * f3.z; acc.w += w3 * f3.w;
    }
    for (; j < j1; j++) {
        int2 r = __ldg(&g_edges[j]);
        float w = __int_as_float(r.y);
        float4 f = __ldg(feat4 + (size_t)r.x * D4 + c);
        acc.x += w * f.x; acc.y += w * f.y; acc.z += w * f.z; acc.w += w * f.w;
    }
    reinterpret_cast<float4*>(g_neighbor)[(size_t)n * D4 + c] = acc;
}

// ---------------------------------------------------------------------------
// K6: GEMM + bias + L2 normalize with packed fma.rn.f32x2.
// Block: 128 threads, tile 128 nodes x 64 cols.
// Thread (tx=t&7, ty=t>>3): 8 nodes (ty*8..) x 8 cols ({4tx..4tx+3, 32+4tx..}).
// xs layout [node][k] pitch 129 (conflict-free broadcast scalar reads),
// ws layout [k][o]   pitch 68  (conflict-free float4 reads).
// ---------------------------------------------------------------------------
#define XP 129
#define WP 68
#define GEMM_SMEM ((128 * XP + 128 * WP) * 4)

#define FFMA2(acc, a, b) \
    asm("fma.rn.f32x2 %0, %1, %2, %0;" : "+l"(acc) : "l"(a), "l"(b))
#define PACK2(dst, lo, hi) \
    asm("mov.b64 %0, {%1, %2};" : "=l"(dst) : "f"(lo), "f"(hi))
#define UNPACK2(lo, hi, src) \
    asm("mov.b64 {%0, %1}, %2;" : "=f"(lo), "=f"(hi) : "l"(src))

__global__ __launch_bounds__(128, 2)
void gemm_norm_kernel(const float4* __restrict__ feat4,
                      const float*  __restrict__ W,
                      const float*  __restrict__ bias,
                      float4*       __restrict__ out4) {
    extern __shared__ float sm[];
    float* xs = sm;              // [128 nodes][XP]
    float* ws = sm + 128 * XP;   // [128 k][WP]

    int t = threadIdx.x;
    int node0 = blockIdx.x * 128;
    const float4* neigh4 = reinterpret_cast<const float4*>(g_neighbor);

    // W[o][k] (64x128 row-major) -> ws[k][o]
    for (int i = t; i < 64 * 128; i += 128) {
        int o = i >> 7, k = i & 127;
        ws[k * WP + o] = __ldg(W + i);
    }
    // x = [feat | neigh] -> xs[n][k]
    for (int idx = t; idx < 128 * 32; idx += 128) {
        int n = idx >> 5, q = idx & 31;
        int node = node0 + n;
        float4 v = make_float4(0.f, 0.f, 0.f, 0.f);
        if (node < N_NODES)
            v = (q < 16) ? __ldg(feat4 + (size_t)node * 16 + q)
                         : neigh4[(size_t)node * 16 + (q - 16)];
        float* xr = xs + n * XP + q * 4;
        xr[0] = v.x; xr[1] = v.y; xr[2] = v.z; xr[3] = v.w;
    }
    __syncthreads();

    int tx = t & 7;
    int ty = t >> 3;

    // 8 nodes x 4 col-pairs of packed accumulators
    unsigned long long acc[8][4];
    {
        float4 bA = *reinterpret_cast<const float4*>(bias + 4 * tx);
        float4 bB = *reinterpret_cast<const float4*>(bias + 32 + 4 * tx);
        unsigned long long b0, b1, b2, b3;
        PACK2(b0, bA.x, bA.y); PACK2(b1, bA.z, bA.w);
        PACK2(b2, bB.x, bB.y); PACK2(b3, bB.z, bB.w);
#pragma unroll
        for (int i = 0; i < 8; i++) {
            acc[i][0] = b0; acc[i][1] = b1; acc[i][2] = b2; acc[i][3] = b3;
        }
    }

    const float* xrow = xs + ty * 8 * XP;
#pragma unroll 2
    for (int k = 0; k < 128; k++) {
        float4 wA = *reinterpret_cast<const float4*>(ws + k * WP + 4 * tx);
        float4 wB = *reinterpret_cast<const float4*>(ws + k * WP + 32 + 4 * tx);
        unsigned long long w0, w1, w2, w3;
        PACK2(w0, wA.x, wA.y); PACK2(w1, wA.z, wA.w);
        PACK2(w2, wB.x, wB.y); PACK2(w3, wB.z, wB.w);
#pragma unroll
        for (int i = 0; i < 8; i++) {
            float x = xrow[i * XP + k];
            unsigned long long xx;
            asm("mov.b64 %0, {%1, %1};" : "=l"(xx) : "f"(x));
            FFMA2(acc[i][0], xx, w0);
            FFMA2(acc[i][1], xx, w1);
            FFMA2(acc[i][2], xx, w2);
            FFMA2(acc[i][3], xx, w3);
        }
    }

    // per-node L2 norm across 8 tx lanes (xor 1,2,4 stays inside tx group)
#pragma unroll
    for (int i = 0; i < 8; i++) {
        float a[8];
        UNPACK2(a[0], a[1], acc[i][0]);
        UNPACK2(a[2], a[3], acc[i][1]);
        UNPACK2(a[4], a[5], acc[i][2]);
        UNPACK2(a[6], a[7], acc[i][3]);
        float ss = 0.f;
#pragma unroll
        for (int j = 0; j < 8; j++) ss += a[j] * a[j];
        ss += __shfl_xor_sync(0xffffffffu, ss, 1);
        ss += __shfl_xor_sync(0xffffffffu, ss, 2);
        ss += __shfl_xor_sync(0xffffffffu, ss, 4);
        float inv = 1.0f / fmaxf(sqrtf(ss), 1e-12f);

        int node = node0 + ty * 8 + i;
        if (node < N_NODES) {
            out4[(size_t)node * 16 + tx] =
                make_float4(a[0] * inv, a[1] * inv, a[2] * inv, a[3] * inv);
            out4[(size_t)node * 16 + 8 + tx] =
                make_float4(a[4] * inv, a[5] * inv, a[6] * inv, a[7] * inv);
        }
    }
}

// ---------------------------------------------------------------------------
// inputs: 0 features[50000,64] f32  1 edge_src[800000] i32  2 edge_dst i32
//         3 edge_weight f32         4 W[64,128] f32         5 b[64] f32
// ---------------------------------------------------------------------------
extern "C" void kernel_launch(void* const* d_in, const int* in_sizes, int n_in,
                              void* d_out, int out_size) {
    const float4* feat4 = (const float4*)d_in[0];
    const int*    esrc  = (const int*)d_in[1];
    const int*    edst  = (const int*)d_in[2];
    const float*  ew    = (const float*)d_in[3];
    const float*  W     = (const float*)d_in[4];
    const float*  bias  = (const float*)d_in[5];
    float4*       out4  = (float4*)d_out;

    cudaFuncSetAttribute(gemm_norm_kernel,
                         cudaFuncAttributeMaxDynamicSharedMemorySize, GEMM_SMEM);

    zero_deg_kernel<<<(N_NODES + 255) / 256, 256>>>();
    hist_kernel<<<(N_EDGES / 4 + 255) / 256, 256>>>((const int4*)edst);
    scan1_kernel<<<196, 256>>>();
    scan2_kernel<<<1, 256>>>();
    scan3_kernel<<<196, 256>>>();
    fill_kernel<<<(N_EDGES / 4 + 255) / 256, 256>>>(
        (const int4*)esrc, (const int4*)edst, (const float4*)ew);
    {
        long long total = (long long)N_NODES * 16;
        gather_kernel<<<(int)((total + 255) / 256), 256>>>(feat4);
    }
    gemm_norm_kernel<<<(N_NODES + 127) / 128, 256 / 2, GEMM_SMEM>>>(feat4, W, bias, out4);

    (void)in_sizes; (void)n_in; (void)out_size;
}

// round 4
// speedup vs baseline: 3.1934x; 1.0408x over previous
#include <cuda_runtime.h>
#include <cuda_fp16.h>

#define N_NODES 50000
#define N_EDGES 800000
#define D 64
#define D4 16
#define SCAN_BLOCKS 196

// ---------------- scratch (device globals; no allocs allowed) ----------------
__device__ int                g_deg[N_NODES];
__device__ int                g_cur[N_NODES];
__device__ int                g_start[N_NODES + 1];
__device__ unsigned long long g_blk_pack[256];        // (flag<<32)|prefix
__device__ int2               g_edges[N_EDGES];       // (src, weight) grouped by dst
__device__ uint4              g_featH4[N_NODES * 8];  // features as fp16, 8 halves/uint4

// ---------------------------------------------------------------------------
// K1: prep — zero degree counters + scan flags, convert features fp32->fp16
// ---------------------------------------------------------------------------
__global__ void prep_kernel(const float4* __restrict__ feat4) {
    int i = blockIdx.x * blockDim.x + threadIdx.x;
    if (i < N_NODES * 8) {
        float4 a = __ldg(feat4 + (size_t)i * 2);
        float4 b = __ldg(feat4 + (size_t)i * 2 + 1);
        uint4 o;
        *(__half2*)&o.x = __floats2half2_rn(a.x, a.y);
        *(__half2*)&o.y = __floats2half2_rn(a.z, a.w);
        *(__half2*)&o.z = __floats2half2_rn(b.x, b.y);
        *(__half2*)&o.w = __floats2half2_rn(b.z, b.w);
        g_featH4[i] = o;
    }
    if (i < N_NODES) g_deg[i] = 0;
    if (i < 256) g_blk_pack[i] = 0ULL;
}

// ---------------------------------------------------------------------------
// K2: histogram of edge destinations (4 edges/thread)
// ---------------------------------------------------------------------------
__global__ void hist_kernel(const int4* __restrict__ edst4) {
    int i = blockIdx.x * blockDim.x + threadIdx.x;
    if (i < N_EDGES / 4) {
        int4 d = __ldg(edst4 + i);
        atomicAdd(&g_deg[d.x], 1);
        atomicAdd(&g_deg[d.y], 1);
        atomicAdd(&g_deg[d.z], 1);
        atomicAdd(&g_deg[d.w], 1);
    }
}

// ---------------------------------------------------------------------------
// K3: single-pass exclusive scan (decoupled lookback), 196 blocks x 256
// ---------------------------------------------------------------------------
__device__ __forceinline__ int block_incl_scan_256(int v, int t, int* warp_sums) {
    int x = v;
#pragma unroll
    for (int off = 1; off < 32; off <<= 1) {
        int y = __shfl_up_sync(0xffffffffu, x, off);
        if ((t & 31) >= off) x += y;
    }
    if ((t & 31) == 31) warp_sums[t >> 5] = x;
    __syncthreads();
    if (t < 8) {
        int s = warp_sums[t];
#pragma unroll
        for (int off = 1; off < 8; off <<= 1) {
            int y = __shfl_up_sync(0x000000ffu, s, off);
            if (t >= off) s += y;
        }
        warp_sums[t] = s;
    }
    __syncthreads();
    if (t >= 32) x += warp_sums[(t >> 5) - 1];
    return x;
}

__global__ void scan_kernel() {
    __shared__ int warp_sums[8];
    __shared__ int s_agg;
    __shared__ int s_excl;
    int t = threadIdx.x, bid = blockIdx.x;
    int i = bid * 256 + t;

    int v = (i < N_NODES) ? g_deg[i] : 0;
    int incl = block_incl_scan_256(v, t, warp_sums);
    if (t == 255) s_agg = incl;
    __syncthreads();
    int agg = s_agg;

    if (t == 0) {   // publish aggregate (block 0 publishes final prefix directly)
        unsigned long long p = (bid == 0)
            ? ((2ULL << 32) | (unsigned)agg)
            : ((1ULL << 32) | (unsigned)agg);
        atomicExch(&g_blk_pack[bid], p);
        if (bid == 0) s_excl = 0;
    }
    if (bid > 0 && t < 32) {   // warp-parallel lookback
        int excl = 0;
        int look = bid - 1;
        while (true) {
            int idx = look - t;
            unsigned long long pk = (idx >= 0) ? atomicAdd(&g_blk_pack[idx], 0ULL)
                                               : (2ULL << 32);
            int f   = (int)(pk >> 32);
            int val = (int)(pk & 0xffffffffULL);
            unsigned ready = __ballot_sync(0xffffffffu, f >= 1);
            if (ready != 0xffffffffu) continue;          // retry window
            unsigned pre = __ballot_sync(0xffffffffu, f == 2);
            if (pre) {
                int firstp = __ffs(pre) - 1;             // nearest prefix
                int contrib = (t <= firstp) ? val : 0;
#pragma unroll
                for (int o = 16; o; o >>= 1) contrib += __shfl_xor_sync(0xffffffffu, contrib, o);
                excl += contrib;
                break;
            } else {
                int contrib = val;
#pragma unroll
                for (int o = 16; o; o >>= 1) contrib += __shfl_xor_sync(0xffffffffu, contrib, o);
                excl += contrib;
                look -= 32;
            }
        }
        if (t == 0) {
            atomicExch(&g_blk_pack[bid], (2ULL << 32) | (unsigned)(excl + agg));
            s_excl = excl;
        }
    }
    __syncthreads();
    int base = s_excl;
    if (i < N_NODES) {
        int s = base + incl - v;
        g_start[i] = s;
        g_cur[i]   = s;
    }
    if (i == 0) g_start[N_NODES] = N_EDGES;
}

// ---------------------------------------------------------------------------
// K4: scatter edge records into CSR slots (4 edges/thread)
// ---------------------------------------------------------------------------
__global__ void fill_kernel(const int4*   __restrict__ esrc4,
                            const int4*   __restrict__ edst4,
                            const float4* __restrict__ ew4) {
    int i = blockIdx.x * blockDim.x + threadIdx.x;
    if (i >= N_EDGES / 4) return;
    int4   s = __ldg(esrc4 + i);
    int4   d = __ldg(edst4 + i);
    float4 w = __ldg(ew4 + i);
    int p0 = atomicAdd(&g_cur[d.x], 1);
    int p1 = atomicAdd(&g_cur[d.y], 1);
    int p2 = atomicAdd(&g_cur[d.z], 1);
    int p3 = atomicAdd(&g_cur[d.w], 1);
    g_edges[p0] = make_int2(s.x, __float_as_int(w.x));
    g_edges[p1] = make_int2(s.y, __float_as_int(w.y));
    g_edges[p2] = make_int2(s.z, __float_as_int(w.z));
    g_edges[p3] = make_int2(s.w, __float_as_int(w.w));
}

// ---------------------------------------------------------------------------
// K5: FUSED gather + GEMM + bias + L2-normalize.
// Block = 256 threads, tile = 128 nodes.
//  phase A: stage W (64x128 -> ws[k][o], pitch 68) + features fp32 into xs[n][0:64]
//  phase B: gather neighbor sums from fp16 features straight into xs[n][64:128]
//           (8 lanes/node, fp32 accumulate, 4 passes of 32 nodes)
//  phase C: register-tiled GEMM with fma.rn.f32x2 + warp-shuffle L2 norm
// xs pitch 132 (mult of 4 for float4; 4-bank stride per node -> conflict-free
// broadcast reads in the k-loop).
// ---------------------------------------------------------------------------
#define XP 132
#define WP 68
#define FUSED_SMEM ((128 * XP + 128 * WP) * 4)

#define FFMA2(acc, a, b) \
    asm("fma.rn.f32x2 %0, %1, %2, %0;" : "+l"(acc) : "l"(a), "l"(b))
#define PACK2(dst, lo, hi) \
    asm("mov.b64 %0, {%1, %2};" : "=l"(dst) : "f"(lo), "f"(hi))
#define UNPACK2(lo, hi, src) \
    asm("mov.b64 {%0, %1}, %2;" : "=f"(lo), "=f"(hi) : "l"(src))

__device__ __forceinline__ void edge_fma(float* a, int2 r, int lane) {
    uint4 h = __ldg(&g_featH4[(size_t)r.x * 8 + lane]);
    float w = __int_as_float(r.y);
    float2 p0 = __half22float2(*(__half2*)&h.x);
    float2 p1 = __half22float2(*(__half2*)&h.y);
    float2 p2 = __half22float2(*(__half2*)&h.z);
    float2 p3 = __half22float2(*(__half2*)&h.w);
    a[0] += w * p0.x; a[1] += w * p0.y;
    a[2] += w * p1.x; a[3] += w * p1.y;
    a[4] += w * p2.x; a[5] += w * p2.y;
    a[6] += w * p3.x; a[7] += w * p3.y;
}

__global__ __launch_bounds__(256, 2)
void fused_kernel(const float4* __restrict__ feat4,
                  const float*  __restrict__ W,
                  const float*  __restrict__ bias,
                  float4*       __restrict__ out4) {
    extern __shared__ float sm[];
    float* xs = sm;              // [128][XP]
    float* ws = sm + 128 * XP;   // [128][WP]

    int t = threadIdx.x;
    int node0 = blockIdx.x * 128;

    // --- phase A: stage W and fp32 features ---
    for (int i = t; i < 64 * 128; i += 256) {
        int o = i >> 7, k = i & 127;
        ws[k * WP + o] = __ldg(W + i);
    }
    for (int idx = t; idx < 128 * 16; idx += 256) {
        int n = idx >> 4, q = idx & 15;
        int node = node0 + n;
        float4 v = make_float4(0.f, 0.f, 0.f, 0.f);
        if (node < N_NODES) v = __ldg(feat4 + (size_t)node * 16 + q);
        *reinterpret_cast<float4*>(xs + n * XP + q * 4) = v;
    }

    // --- phase B: gather neighbor sums (8 lanes/node) ---
    {
        int lane = t & 7;     // 8-half chunk within the 64-wide row
        int nl   = t >> 3;    // 0..31
#pragma unroll
        for (int pass = 0; pass < 4; pass++) {
            int n_local = pass * 32 + nl;
            int node = node0 + n_local;
            float a[8] = {0.f, 0.f, 0.f, 0.f, 0.f, 0.f, 0.f, 0.f};
            if (node < N_NODES) {
                int j  = g_start[node];
                int j1 = g_start[node + 1];
                for (; j + 4 <= j1; j += 4) {
                    int2 r0 = __ldg(&g_edges[j + 0]);
                    int2 r1 = __ldg(&g_edges[j + 1]);
                    int2 r2 = __ldg(&g_edges[j + 2]);
                    int2 r3 = __ldg(&g_edges[j + 3]);
                    edge_fma(a, r0, lane);
                    edge_fma(a, r1, lane);
                    edge_fma(a, r2, lane);
                    edge_fma(a, r3, lane);
                }
                for (; j < j1; j++) edge_fma(a, __ldg(&g_edges[j]), lane);
            }
            float* dst = xs + n_local * XP + 64 + lane * 8;
            *reinterpret_cast<float4*>(dst)     = make_float4(a[0], a[1], a[2], a[3]);
            *reinterpret_cast<float4*>(dst + 4) = make_float4(a[4], a[5], a[6], a[7]);
        }
    }
    __syncthreads();

    // --- phase C: GEMM (4 nodes x 8 cols per thread) + norm ---
    int tx = t & 7;    // col quad
    int ty = t >> 3;   // 0..31, nodes ty*4 .. ty*4+3

    unsigned long long acc[4][4];
    {
        float4 bA = *reinterpret_cast<const float4*>(bias + 4 * tx);
        float4 bB = *reinterpret_cast<const float4*>(bias + 32 + 4 * tx);
        unsigned long long b0, b1, b2, b3;
        PACK2(b0, bA.x, bA.y); PACK2(b1, bA.z, bA.w);
        PACK2(b2, bB.x, bB.y); PACK2(b3, bB.z, bB.w);
#pragma unroll
        for (int i = 0; i < 4; i++) {
            acc[i][0] = b0; acc[i][1] = b1; acc[i][2] = b2; acc[i][3] = b3;
        }
    }

    const float* xrow = xs + ty * 4 * XP;
#pragma unroll 4
    for (int k = 0; k < 128; k++) {
        float4 wA = *reinterpret_cast<const float4*>(ws + k * WP + 4 * tx);
        float4 wB = *reinterpret_cast<const float4*>(ws + k * WP + 32 + 4 * tx);
        unsigned long long w0, w1, w2, w3;
        PACK2(w0, wA.x, wA.y); PACK2(w1, wA.z, wA.w);
        PACK2(w2, wB.x, wB.y); PACK2(w3, wB.z, wB.w);
#pragma unroll
        for (int i = 0; i < 4; i++) {
            float x = xrow[i * XP + k];
            unsigned long long xx;
            asm("mov.b64 %0, {%1, %1};" : "=l"(xx) : "f"(x));
            FFMA2(acc[i][0], xx, w0);
            FFMA2(acc[i][1], xx, w1);
            FFMA2(acc[i][2], xx, w2);
            FFMA2(acc[i][3], xx, w3);
        }
    }

#pragma unroll
    for (int i = 0; i < 4; i++) {
        float a[8];
        UNPACK2(a[0], a[1], acc[i][0]);
        UNPACK2(a[2], a[3], acc[i][1]);
        UNPACK2(a[4], a[5], acc[i][2]);
        UNPACK2(a[6], a[7], acc[i][3]);
        float ss = 0.f;
#pragma unroll
        for (int j = 0; j < 8; j++) ss += a[j] * a[j];
        ss += __shfl_xor_sync(0xffffffffu, ss, 1);
        ss += __shfl_xor_sync(0xffffffffu, ss, 2);
        ss += __shfl_xor_sync(0xffffffffu, ss, 4);
        float inv = 1.0f / fmaxf(sqrtf(ss), 1e-12f);

        int node = node0 + ty * 4 + i;
        if (node < N_NODES) {
            out4[(size_t)node * 16 + tx] =
                make_float4(a[0] * inv, a[1] * inv, a[2] * inv, a[3] * inv);
            out4[(size_t)node * 16 + 8 + tx] =
                make_float4(a[4] * inv, a[5] * inv, a[6] * inv, a[7] * inv);
        }
    }
}

// ---------------------------------------------------------------------------
// inputs: 0 features[50000,64] f32  1 edge_src[800000] i32  2 edge_dst i32
//         3 edge_weight f32         4 W[64,128] f32         5 b[64] f32
// ---------------------------------------------------------------------------
extern "C" void kernel_launch(void* const* d_in, const int* in_sizes, int n_in,
                              void* d_out, int out_size) {
    const float4* feat4 = (const float4*)d_in[0];
    const int*    esrc  = (const int*)d_in[1];
    const int*    edst  = (const int*)d_in[2];
    const float*  ew    = (const float*)d_in[3];
    const float*  W     = (const float*)d_in[4];
    const float*  bias  = (const float*)d_in[5];
    float4*       out4  = (float4*)d_out;

    cudaFuncSetAttribute(fused_kernel,
                         cudaFuncAttributeMaxDynamicSharedMemorySize, FUSED_SMEM);

    prep_kernel<<<(N_NODES * 8 + 255) / 256, 256>>>(feat4);
    hist_kernel<<<(N_EDGES / 4 + 255) / 256, 256>>>((const int4*)edst);
    scan_kernel<<<SCAN_BLOCKS, 256>>>();
    fill_kernel<<<(N_EDGES / 4 + 255) / 256, 256>>>(
        (const int4*)esrc, (const int4*)edst, (const float4*)ew);
    fused_kernel<<<(N_NODES + 127) / 128, 256, FUSED_SMEM>>>(feat4, W, bias, out4);

    (void)in_sizes; (void)n_in; (void)out_size;
}

// round 5
// speedup vs baseline: 3.5457x; 1.1103x over previous
#include <cuda_runtime.h>
#include <cuda_fp16.h>

#define N_NODES 50000
#define N_EDGES 800000
#define D 64
#define SCAN_BLOCKS 196
#define N_TILES 391              // ceil(50000/128)
#define FUSED_GRID 296           // 2 blocks/SM * 148 SMs

// ---------------- scratch (device globals; no allocs allowed) ----------------
// All mutable state is zero at process start (static init) and re-zeroed by
// fill_kernel each replay, so every graph replay sees identical initial state.
__device__ int                g_deg[N_NODES];
__device__ int                g_start[N_NODES + 1];
__device__ int                g_rank[N_EDGES];
__device__ unsigned long long g_blk_pack[256];        // (flag<<32)|value
__device__ int                g_tile;                 // fused tile counter
__device__ int2               g_edges[N_EDGES];       // (src, weight) grouped by dst
__device__ uint4              g_featH4[N_NODES * 8];  // fp16 features, 8 halves/uint4

// ---------------------------------------------------------------------------
// K1: fp32->fp16 feature convert + rank-capturing destination histogram.
// g_deg must be zero on entry (static init / re-zeroed by fill_kernel).
// ---------------------------------------------------------------------------
__global__ void conv_hist_kernel(const float4* __restrict__ feat4,
                                 const int4*   __restrict__ edst4,
                                 int4*         __restrict__ rank4) {
    int i = blockIdx.x * blockDim.x + threadIdx.x;
    if (i < N_NODES * 8) {
        float4 a = __ldg(feat4 + (size_t)i * 2);
        float4 b = __ldg(feat4 + (size_t)i * 2 + 1);
        uint4 o;
        *(__half2*)&o.x = __floats2half2_rn(a.x, a.y);
        *(__half2*)&o.y = __floats2half2_rn(a.z, a.w);
        *(__half2*)&o.z = __floats2half2_rn(b.x, b.y);
        *(__half2*)&o.w = __floats2half2_rn(b.z, b.w);
        g_featH4[i] = o;
    }
    if (i < N_EDGES / 4) {
        int4 d = __ldg(edst4 + i);
        int4 r;
        r.x = atomicAdd(&g_deg[d.x], 1);
        r.y = atomicAdd(&g_deg[d.y], 1);
        r.z = atomicAdd(&g_deg[d.z], 1);
        r.w = atomicAdd(&g_deg[d.w], 1);
        rank4[i] = r;
    }
}

// ---------------------------------------------------------------------------
// K2: single-pass exclusive scan (decoupled lookback), 196 blocks x 256
// ---------------------------------------------------------------------------
__device__ __forceinline__ int block_incl_scan_256(int v, int t, int* warp_sums) {
    int x = v;
#pragma unroll
    for (int off = 1; off < 32; off <<= 1) {
        int y = __shfl_up_sync(0xffffffffu, x, off);
        if ((t & 31) >= off) x += y;
    }
    if ((t & 31) == 31) warp_sums[t >> 5] = x;
    __syncthreads();
    if (t < 8) {
        int s = warp_sums[t];
#pragma unroll
        for (int off = 1; off < 8; off <<= 1) {
            int y = __shfl_up_sync(0x000000ffu, s, off);
            if (t >= off) s += y;
        }
        warp_sums[t] = s;
    }
    __syncthreads();
    if (t >= 32) x += warp_sums[(t >> 5) - 1];
    return x;
}

__global__ void scan_kernel() {
    __shared__ int warp_sums[8];
    __shared__ int s_agg;
    __shared__ int s_excl;
    int t = threadIdx.x, bid = blockIdx.x;
    int i = bid * 256 + t;

    int v = (i < N_NODES) ? g_deg[i] : 0;
    int incl = block_incl_scan_256(v, t, warp_sums);
    if (t == 255) s_agg = incl;
    __syncthreads();
    int agg = s_agg;

    if (t == 0) {
        unsigned long long p = (bid == 0)
            ? ((2ULL << 32) | (unsigned)agg)
            : ((1ULL << 32) | (unsigned)agg);
        atomicExch(&g_blk_pack[bid], p);
        if (bid == 0) s_excl = 0;
    }
    if (bid > 0 && t < 32) {
        int excl = 0;
        int look = bid - 1;
        while (true) {
            int idx = look - t;
            unsigned long long pk = (idx >= 0) ? atomicAdd(&g_blk_pack[idx], 0ULL)
                                               : (2ULL << 32);
            int f   = (int)(pk >> 32);
            int val = (int)(pk & 0xffffffffULL);
            unsigned ready = __ballot_sync(0xffffffffu, f >= 1);
            if (ready != 0xffffffffu) continue;
            unsigned pre = __ballot_sync(0xffffffffu, f == 2);
            if (pre) {
                int firstp = __ffs(pre) - 1;
                int contrib = (t <= firstp) ? val : 0;
#pragma unroll
                for (int o = 16; o; o >>= 1) contrib += __shfl_xor_sync(0xffffffffu, contrib, o);
                excl += contrib;
                break;
            } else {
                int contrib = val;
#pragma unroll
                for (int o = 16; o; o >>= 1) contrib += __shfl_xor_sync(0xffffffffu, contrib, o);
                excl += contrib;
                look -= 32;
            }
        }
        if (t == 0) {
            atomicExch(&g_blk_pack[bid], (2ULL << 32) | (unsigned)(excl + agg));
            s_excl = excl;
        }
    }
    __syncthreads();
    int base = s_excl;
    if (i < N_NODES) g_start[i] = base + incl - v;
    if (i == 0) g_start[N_NODES] = N_EDGES;
}

// ---------------------------------------------------------------------------
// K3: atomic-free CSR fill (slot = g_start[dst] + rank), plus state re-zero
// for the next graph replay (g_deg / g_blk_pack / g_tile).
// ---------------------------------------------------------------------------
__global__ void fill_kernel(const int4*   __restrict__ esrc4,
                            const int4*   __restrict__ edst4,
                            const float4* __restrict__ ew4,
                            const int4*   __restrict__ rank4) {
    int i = blockIdx.x * blockDim.x + threadIdx.x;
    if (i < N_EDGES / 4) {
        int4   s = __ldg(esrc4 + i);
        int4   d = __ldg(edst4 + i);
        float4 w = __ldg(ew4 + i);
        int4   r = __ldg(rank4 + i);
        g_edges[g_start[d.x] + r.x] = make_int2(s.x, __float_as_int(w.x));
        g_edges[g_start[d.y] + r.y] = make_int2(s.y, __float_as_int(w.y));
        g_edges[g_start[d.z] + r.z] = make_int2(s.z, __float_as_int(w.z));
        g_edges[g_start[d.w] + r.w] = make_int2(s.w, __float_as_int(w.w));
    }
    if (i < N_NODES) g_deg[i] = 0;
    if (i < 256) g_blk_pack[i] = 0ULL;
    if (i == 0) g_tile = 0;
}

// ---------------------------------------------------------------------------
// K4: PERSISTENT fused gather + GEMM + bias + L2-normalize.
// Grid = 296 blocks x 256 threads; tiles (128 nodes) pulled via atomic counter.
// W staged once per block. Per tile:
//   phase A: features fp32 -> xs[n][0:64]
//   phase B: neighbor gather from fp16 features -> xs[n][64:128] (8 lanes/node)
//   phase C: register GEMM with fma.rn.f32x2 + warp-shuffle L2 norm
// ---------------------------------------------------------------------------
#define XP 132
#define WP 68
#define FUSED_SMEM ((128 * XP + 128 * WP) * 4)

#define FFMA2(acc, a, b) \
    asm("fma.rn.f32x2 %0, %1, %2, %0;" : "+l"(acc) : "l"(a), "l"(b))
#define PACK2(dst, lo, hi) \
    asm("mov.b64 %0, {%1, %2};" : "=l"(dst) : "f"(lo), "f"(hi))
#define UNPACK2(lo, hi, src) \
    asm("mov.b64 {%0, %1}, %2;" : "=f"(lo), "=f"(hi) : "l"(src))

__device__ __forceinline__ void edge_fma(float* a, int2 r, int lane) {
    uint4 h = __ldg(&g_featH4[(size_t)r.x * 8 + lane]);
    float w = __int_as_float(r.y);
    float2 p0 = __half22float2(*(__half2*)&h.x);
    float2 p1 = __half22float2(*(__half2*)&h.y);
    float2 p2 = __half22float2(*(__half2*)&h.z);
    float2 p3 = __half22float2(*(__half2*)&h.w);
    a[0] += w * p0.x; a[1] += w * p0.y;
    a[2] += w * p1.x; a[3] += w * p1.y;
    a[4] += w * p2.x; a[5] += w * p2.y;
    a[6] += w * p3.x; a[7] += w * p3.y;
}

__global__ __launch_bounds__(256, 2)
void fused_kernel(const float4* __restrict__ feat4,
                  const float*  __restrict__ W,
                  const float*  __restrict__ bias,
                  float4*       __restrict__ out4) {
    extern __shared__ float sm[];
    float* xs = sm;              // [128][XP]
    float* ws = sm + 128 * XP;   // [128][WP]
    __shared__ int s_tile;

    int t = threadIdx.x;
    int tx = t & 7;
    int ty = t >> 3;

    // W[o][k] (64x128 row-major) -> ws[k][o], once per block
    for (int i = t; i < 64 * 128; i += 256) {
        int o = i >> 7, k = i & 127;
        ws[k * WP + o] = __ldg(W + i);
    }
    // bias, packed once
    unsigned long long b0, b1, b2, b3;
    {
        float4 bA = *reinterpret_cast<const float4*>(bias + 4 * tx);
        float4 bB = *reinterpret_cast<const float4*>(bias + 32 + 4 * tx);
        PACK2(b0, bA.x, bA.y); PACK2(b1, bA.z, bA.w);
        PACK2(b2, bB.x, bB.y); PACK2(b3, bB.z, bB.w);
    }

    while (true) {
        if (t == 0) s_tile = atomicAdd(&g_tile, 1);
        __syncthreads();
        int tile = s_tile;
        __syncthreads();          // everyone read s_tile before next overwrite
        if (tile >= N_TILES) break;
        int node0 = tile * 128;

        // --- phase A: fp32 self features -> xs[n][0:64] ---
        for (int idx = t; idx < 128 * 16; idx += 256) {
            int n = idx >> 4, q = idx & 15;
            int node = node0 + n;
            float4 v = make_float4(0.f, 0.f, 0.f, 0.f);
            if (node < N_NODES) v = __ldg(feat4 + (size_t)node * 16 + q);
            *reinterpret_cast<float4*>(xs + n * XP + q * 4) = v;
        }

        // --- phase B: neighbor gather -> xs[n][64:128] ---
        {
            int lane = t & 7;
            int nl   = t >> 3;
#pragma unroll
            for (int pass = 0; pass < 4; pass++) {
                int n_local = pass * 32 + nl;
                int node = node0 + n_local;
                float a[8] = {0.f, 0.f, 0.f, 0.f, 0.f, 0.f, 0.f, 0.f};
                if (node < N_NODES) {
                    int j  = g_start[node];
                    int j1 = g_start[node + 1];
                    for (; j + 4 <= j1; j += 4) {
                        int2 r0 = __ldg(&g_edges[j + 0]);
                        int2 r1 = __ldg(&g_edges[j + 1]);
                        int2 r2 = __ldg(&g_edges[j + 2]);
                        int2 r3 = __ldg(&g_edges[j + 3]);
                        edge_fma(a, r0, lane);
                        edge_fma(a, r1, lane);
                        edge_fma(a, r2, lane);
                        edge_fma(a, r3, lane);
                    }
                    for (; j < j1; j++) edge_fma(a, __ldg(&g_edges[j]), lane);
                }
                float* dst = xs + n_local * XP + 64 + lane * 8;
                *reinterpret_cast<float4*>(dst)     = make_float4(a[0], a[1], a[2], a[3]);
                *reinterpret_cast<float4*>(dst + 4) = make_float4(a[4], a[5], a[6], a[7]);
            }
        }
        __syncthreads();

        // --- phase C: GEMM (4 nodes x 8 cols per thread) + norm ---
        unsigned long long acc[4][4];
#pragma unroll
        for (int i = 0; i < 4; i++) {
            acc[i][0] = b0; acc[i][1] = b1; acc[i][2] = b2; acc[i][3] = b3;
        }

        const float* xrow = xs + ty * 4 * XP;
#pragma unroll 4
        for (int k = 0; k < 128; k++) {
            float4 wA = *reinterpret_cast<const float4*>(ws + k * WP + 4 * tx);
            float4 wB = *reinterpret_cast<const float4*>(ws + k * WP + 32 + 4 * tx);
            unsigned long long w0, w1, w2, w3;
            PACK2(w0, wA.x, wA.y); PACK2(w1, wA.z, wA.w);
            PACK2(w2, wB.x, wB.y); PACK2(w3, wB.z, wB.w);
#pragma unroll
            for (int i = 0; i < 4; i++) {
                float x = xrow[i * XP + k];
                unsigned long long xx;
                asm("mov.b64 %0, {%1, %1};" : "=l"(xx) : "f"(x));
                FFMA2(acc[i][0], xx, w0);
                FFMA2(acc[i][1], xx, w1);
                FFMA2(acc[i][2], xx, w2);
                FFMA2(acc[i][3], xx, w3);
            }
        }

#pragma unroll
        for (int i = 0; i < 4; i++) {
            float a[8];
            UNPACK2(a[0], a[1], acc[i][0]);
            UNPACK2(a[2], a[3], acc[i][1]);
            UNPACK2(a[4], a[5], acc[i][2]);
            UNPACK2(a[6], a[7], acc[i][3]);
            float ss = 0.f;
#pragma unroll
            for (int j = 0; j < 8; j++) ss += a[j] * a[j];
            ss += __shfl_xor_sync(0xffffffffu, ss, 1);
            ss += __shfl_xor_sync(0xffffffffu, ss, 2);
            ss += __shfl_xor_sync(0xffffffffu, ss, 4);
            float inv = 1.0f / fmaxf(sqrtf(ss), 1e-12f);

            int node = node0 + ty * 4 + i;
            if (node < N_NODES) {
                out4[(size_t)node * 16 + tx] =
                    make_float4(a[0] * inv, a[1] * inv, a[2] * inv, a[3] * inv);
                out4[(size_t)node * 16 + 8 + tx] =
                    make_float4(a[4] * inv, a[5] * inv, a[6] * inv, a[7] * inv);
            }
        }
        __syncthreads();   // xs reuse barrier before next tile
    }
}

// ---------------------------------------------------------------------------
// inputs: 0 features[50000,64] f32  1 edge_src[800000] i32  2 edge_dst i32
//         3 edge_weight f32         4 W[64,128] f32         5 b[64] f32
// ---------------------------------------------------------------------------
extern "C" void kernel_launch(void* const* d_in, const int* in_sizes, int n_in,
                              void* d_out, int out_size) {
    const float4* feat4 = (const float4*)d_in[0];
    const int*    esrc  = (const int*)d_in[1];
    const int*    edst  = (const int*)d_in[2];
    const float*  ew    = (const float*)d_in[3];
    const float*  W     = (const float*)d_in[4];
    const float*  bias  = (const float*)d_in[5];
    float4*       out4  = (float4*)d_out;

    cudaFuncSetAttribute(fused_kernel,
                         cudaFuncAttributeMaxDynamicSharedMemorySize, FUSED_SMEM);

    int4* rank4;
    cudaGetSymbolAddress((void**)&rank4, g_rank);

    conv_hist_kernel<<<(N_NODES * 8 + 255) / 256, 256>>>(
        feat4, (const int4*)edst, rank4);
    scan_kernel<<<SCAN_BLOCKS, 256>>>();
    fill_kernel<<<(N_EDGES / 4 + 255) / 256, 256>>>(
        (const int4*)esrc, (const int4*)edst, (const float4*)ew,
        (const int4*)rank4);
    fused_kernel<<<FUSED_GRID, 256, FUSED_SMEM>>>(feat4, W, bias, out4);

    (void)in_sizes; (void)n_in; (void)out_size;
}

// round 6
// speedup vs baseline: 3.9593x; 1.1166x over previous
#include <cuda_runtime.h>
#include <cuda_fp16.h>

#define N_NODES 50000
#define N_EDGES 800000
#define D 64
#define SCAN_BLOCKS 196
#define N_TILES 391              // ceil(50000/128)

// ---------------- scratch (device globals; no allocs allowed) ----------------
// Mutable state is zero at process start (static init) and re-zeroed by
// fill_kernel each replay, so every graph replay sees identical initial state.
__device__ int                g_deg[N_NODES];
__device__ int                g_start[N_NODES + 1];
__device__ int                g_rank[N_EDGES];
__device__ unsigned long long g_blk_pack[256];        // (flag<<32)|value
__device__ int2               g_edges[N_EDGES];       // (src, weight) grouped by dst
__device__ uint4              g_featH4[N_NODES * 8];  // fp16 features, 8 halves/uint4
__device__ float4             g_neighbor[N_NODES * 16];

// ---------------------------------------------------------------------------
// K1: fp32->fp16 feature convert + rank-capturing destination histogram.
// ---------------------------------------------------------------------------
__global__ void conv_hist_kernel(const float4* __restrict__ feat4,
                                 const int4*   __restrict__ edst4,
                                 int4*         __restrict__ rank4) {
    int i = blockIdx.x * blockDim.x + threadIdx.x;
    if (i < N_NODES * 8) {
        float4 a = __ldg(feat4 + (size_t)i * 2);
        float4 b = __ldg(feat4 + (size_t)i * 2 + 1);
        uint4 o;
        *(__half2*)&o.x = __floats2half2_rn(a.x, a.y);
        *(__half2*)&o.y = __floats2half2_rn(a.z, a.w);
        *(__half2*)&o.z = __floats2half2_rn(b.x, b.y);
        *(__half2*)&o.w = __floats2half2_rn(b.z, b.w);
        g_featH4[i] = o;
    }
    if (i < N_EDGES / 4) {
        int4 d = __ldg(edst4 + i);
        int4 r;
        r.x = atomicAdd(&g_deg[d.x], 1);
        r.y = atomicAdd(&g_deg[d.y], 1);
        r.z = atomicAdd(&g_deg[d.z], 1);
        r.w = atomicAdd(&g_deg[d.w], 1);
        rank4[i] = r;
    }
}

// ---------------------------------------------------------------------------
// K2: single-pass exclusive scan (decoupled lookback), 196 blocks x 256
// ---------------------------------------------------------------------------
__device__ __forceinline__ int block_incl_scan_256(int v, int t, int* warp_sums) {
    int x = v;
#pragma unroll
    for (int off = 1; off < 32; off <<= 1) {
        int y = __shfl_up_sync(0xffffffffu, x, off);
        if ((t & 31) >= off) x += y;
    }
    if ((t & 31) == 31) warp_sums[t >> 5] = x;
    __syncthreads();
    if (t < 8) {
        int s = warp_sums[t];
#pragma unroll
        for (int off = 1; off < 8; off <<= 1) {
            int y = __shfl_up_sync(0x000000ffu, s, off);
            if (t >= off) s += y;
        }
        warp_sums[t] = s;
    }
    __syncthreads();
    if (t >= 32) x += warp_sums[(t >> 5) - 1];
    return x;
}

__global__ void scan_kernel() {
    __shared__ int warp_sums[8];
    __shared__ int s_agg;
    __shared__ int s_excl;
    int t = threadIdx.x, bid = blockIdx.x;
    int i = bid * 256 + t;

    int v = (i < N_NODES) ? g_deg[i] : 0;
    int incl = block_incl_scan_256(v, t, warp_sums);
    if (t == 255) s_agg = incl;
    __syncthreads();
    int agg = s_agg;

    if (t == 0) {
        unsigned long long p = (bid == 0)
            ? ((2ULL << 32) | (unsigned)agg)
            : ((1ULL << 32) | (unsigned)agg);
        atomicExch(&g_blk_pack[bid], p);
        if (bid == 0) s_excl = 0;
    }
    if (bid > 0 && t < 32) {
        int excl = 0;
        int look = bid - 1;
        while (true) {
            int idx = look - t;
            unsigned long long pk = (idx >= 0) ? atomicAdd(&g_blk_pack[idx], 0ULL)
                                               : (2ULL << 32);
            int f   = (int)(pk >> 32);
            int val = (int)(pk & 0xffffffffULL);
            unsigned ready = __ballot_sync(0xffffffffu, f >= 1);
            if (ready != 0xffffffffu) continue;
            unsigned pre = __ballot_sync(0xffffffffu, f == 2);
            if (pre) {
                int firstp = __ffs(pre) - 1;
                int contrib = (t <= firstp) ? val : 0;
#pragma unroll
                for (int o = 16; o; o >>= 1) contrib += __shfl_xor_sync(0xffffffffu, contrib, o);
                excl += contrib;
                break;
            } else {
                int contrib = val;
#pragma unroll
                for (int o = 16; o; o >>= 1) contrib += __shfl_xor_sync(0xffffffffu, contrib, o);
                excl += contrib;
                look -= 32;
            }
        }
        if (t == 0) {
            atomicExch(&g_blk_pack[bid], (2ULL << 32) | (unsigned)(excl + agg));
            s_excl = excl;
        }
    }
    __syncthreads();
    int base = s_excl;
    if (i < N_NODES) g_start[i] = base + incl - v;
    if (i == 0) g_start[N_NODES] = N_EDGES;
}

// ---------------------------------------------------------------------------
// K3: atomic-free CSR fill (slot = g_start[dst] + rank) + state re-zero.
// ---------------------------------------------------------------------------
__global__ void fill_kernel(const int4*   __restrict__ esrc4,
                            const int4*   __restrict__ edst4,
                            const float4* __restrict__ ew4,
                            const int4*   __restrict__ rank4) {
    int i = blockIdx.x * blockDim.x + threadIdx.x;
    if (i < N_EDGES / 4) {
        int4   s = __ldg(esrc4 + i);
        int4   d = __ldg(edst4 + i);
        float4 w = __ldg(ew4 + i);
        int4   r = __ldg(rank4 + i);
        g_edges[g_start[d.x] + r.x] = make_int2(s.x, __float_as_int(w.x));
        g_edges[g_start[d.y] + r.y] = make_int2(s.y, __float_as_int(w.y));
        g_edges[g_start[d.z] + r.z] = make_int2(s.z, __float_as_int(w.z));
        g_edges[g_start[d.w] + r.w] = make_int2(s.w, __float_as_int(w.w));
    }
    if (i < N_NODES) g_deg[i] = 0;
    if (i < 256) g_blk_pack[i] = 0ULL;
}

// ---------------------------------------------------------------------------
// K4: high-occupancy gather. 8 lanes/node, no smem, x4 edge unroll (8 loads
// in flight per thread). fp16 feature rows, fp32 accumulate -> g_neighbor.
// ---------------------------------------------------------------------------
__device__ __forceinline__ void edge_fma(float* a, int2 r, int lane) {
    uint4 h = __ldg(&g_featH4[(size_t)r.x * 8 + lane]);
    float w = __int_as_float(r.y);
    float2 p0 = __half22float2(*(__half2*)&h.x);
    float2 p1 = __half22float2(*(__half2*)&h.y);
    float2 p2 = __half22float2(*(__half2*)&h.z);
    float2 p3 = __half22float2(*(__half2*)&h.w);
    a[0] += w * p0.x; a[1] += w * p0.y;
    a[2] += w * p1.x; a[3] += w * p1.y;
    a[4] += w * p2.x; a[5] += w * p2.y;
    a[6] += w * p3.x; a[7] += w * p3.y;
}

__global__ void gather_kernel() {
    int t = blockIdx.x * blockDim.x + threadIdx.x;
    int n    = t >> 3;
    int lane = t & 7;
    if (n >= N_NODES) return;

    float a[8] = {0.f, 0.f, 0.f, 0.f, 0.f, 0.f, 0.f, 0.f};
    int j  = g_start[n];
    int j1 = g_start[n + 1];
    for (; j + 4 <= j1; j += 4) {
        int2 r0 = __ldg(&g_edges[j + 0]);
        int2 r1 = __ldg(&g_edges[j + 1]);
        int2 r2 = __ldg(&g_edges[j + 2]);
        int2 r3 = __ldg(&g_edges[j + 3]);
        edge_fma(a, r0, lane);
        edge_fma(a, r1, lane);
        edge_fma(a, r2, lane);
        edge_fma(a, r3, lane);
    }
    for (; j < j1; j++) edge_fma(a, __ldg(&g_edges[j]), lane);

    g_neighbor[(size_t)n * 16 + lane * 2]     = make_float4(a[0], a[1], a[2], a[3]);
    g_neighbor[(size_t)n * 16 + lane * 2 + 1] = make_float4(a[4], a[5], a[6], a[7]);
}

// ---------------------------------------------------------------------------
// K5: GEMM + bias + L2-normalize, k-split staging for 3 blocks/SM.
// 391 blocks x 256 threads, 128-node tile each (single wave at occ 3).
// ws[k][o] pitch 68 (34.8 KB); xs[n][64k-half] pitch 68 (34.8 KB).
// Half 1 = features (k 0..63), half 2 = neighbor (k 64..127); accumulators
// live in registers across both halves. fma.rn.f32x2 packed math.
// ---------------------------------------------------------------------------
#define XP 68
#define WP 68
#define GEMM_SMEM ((128 * XP + 128 * WP) * 4)

#define FFMA2(acc, a, b) \
    asm("fma.rn.f32x2 %0, %1, %2, %0;" : "+l"(acc) : "l"(a), "l"(b))
#define PACK2(dst, lo, hi) \
    asm("mov.b64 %0, {%1, %2};" : "=l"(dst) : "f"(lo), "f"(hi))
#define UNPACK2(lo, hi, src) \
    asm("mov.b64 {%0, %1}, %2;" : "=f"(lo), "=f"(hi) : "l"(src))

__global__ __launch_bounds__(256, 3)
void gemm_norm_kernel(const float4* __restrict__ feat4,
                      const float*  __restrict__ W,
                      const float*  __restrict__ bias,
                      float4*       __restrict__ out4) {
    extern __shared__ float sm[];
    float* xs = sm;              // [128 nodes][XP]  (one 64-k half at a time)
    float* ws = sm + 128 * XP;   // [128 k][WP]

    int t = threadIdx.x;
    int tx = t & 7;
    int ty = t >> 3;
    int node0 = blockIdx.x * 128;

    // W[o][k] (64x128 row-major) -> ws[k][o]
    for (int i = t; i < 64 * 128; i += 256) {
        int o = i >> 7, k = i & 127;
        ws[k * WP + o] = __ldg(W + i);
    }

    unsigned long long acc[4][4];
    {
        float4 bA = *reinterpret_cast<const float4*>(bias + 4 * tx);
        float4 bB = *reinterpret_cast<const float4*>(bias + 32 + 4 * tx);
        unsigned long long b0, b1, b2, b3;
        PACK2(b0, bA.x, bA.y); PACK2(b1, bA.z, bA.w);
        PACK2(b2, bB.x, bB.y); PACK2(b3, bB.z, bB.w);
#pragma unroll
        for (int i = 0; i < 4; i++) {
            acc[i][0] = b0; acc[i][1] = b1; acc[i][2] = b2; acc[i][3] = b3;
        }
    }

#pragma unroll
    for (int half = 0; half < 2; half++) {
        // stage this half's x: features (half 0) or neighbor (half 1)
        const float4* src = (half == 0) ? feat4 : g_neighbor;
        __syncthreads();   // previous half's reads done before overwrite
        for (int idx = t; idx < 128 * 16; idx += 256) {
            int n = idx >> 4, q = idx & 15;
            int node = node0 + n;
            float4 v = make_float4(0.f, 0.f, 0.f, 0.f);
            if (node < N_NODES) v = __ldg(src + (size_t)node * 16 + q);
            *reinterpret_cast<float4*>(xs + n * XP + q * 4) = v;
        }
        __syncthreads();

        const float* xrow = xs + ty * 4 * XP;
        const float* wsh  = ws + half * 64 * WP;
#pragma unroll 4
        for (int k = 0; k < 64; k++) {
            float4 wA = *reinterpret_cast<const float4*>(wsh + k * WP + 4 * tx);
            float4 wB = *reinterpret_cast<const float4*>(wsh + k * WP + 32 + 4 * tx);
            unsigned long long w0, w1, w2, w3;
            PACK2(w0, wA.x, wA.y); PACK2(w1, wA.z, wA.w);
            PACK2(w2, wB.x, wB.y); PACK2(w3, wB.z, wB.w);
#pragma unroll
            for (int i = 0; i < 4; i++) {
                float x = xrow[i * XP + k];
                unsigned long long xx;
                asm("mov.b64 %0, {%1, %1};" : "=l"(xx) : "f"(x));
                FFMA2(acc[i][0], xx, w0);
                FFMA2(acc[i][1], xx, w1);
                FFMA2(acc[i][2], xx, w2);
                FFMA2(acc[i][3], xx, w3);
            }
        }
    }

#pragma unroll
    for (int i = 0; i < 4; i++) {
        float a[8];
        UNPACK2(a[0], a[1], acc[i][0]);
        UNPACK2(a[2], a[3], acc[i][1]);
        UNPACK2(a[4], a[5], acc[i][2]);
        UNPACK2(a[6], a[7], acc[i][3]);
        float ss = 0.f;
#pragma unroll
        for (int j = 0; j < 8; j++) ss += a[j] * a[j];
        ss += __shfl_xor_sync(0xffffffffu, ss, 1);
        ss += __shfl_xor_sync(0xffffffffu, ss, 2);
        ss += __shfl_xor_sync(0xffffffffu, ss, 4);
        float inv = 1.0f / fmaxf(sqrtf(ss), 1e-12f);

        int node = node0 + ty * 4 + i;
        if (node < N_NODES) {
            out4[(size_t)node * 16 + tx] =
                make_float4(a[0] * inv, a[1] * inv, a[2] * inv, a[3] * inv);
            out4[(size_t)node * 16 + 8 + tx] =
                make_float4(a[4] * inv, a[5] * inv, a[6] * inv, a[7] * inv);
        }
    }
}

// ---------------------------------------------------------------------------
// inputs: 0 features[50000,64] f32  1 edge_src[800000] i32  2 edge_dst i32
//         3 edge_weight f32         4 W[64,128] f32         5 b[64] f32
// ---------------------------------------------------------------------------
extern "C" void kernel_launch(void* const* d_in, const int* in_sizes, int n_in,
                              void* d_out, int out_size) {
    const float4* feat4 = (const float4*)d_in[0];
    const int*    esrc  = (const int*)d_in[1];
    const int*    edst  = (const int*)d_in[2];
    const float*  ew    = (const float*)d_in[3];
    const float*  W     = (const float*)d_in[4];
    const float*  bias  = (const float*)d_in[5];
    float4*       out4  = (float4*)d_out;

    cudaFuncSetAttribute(gemm_norm_kernel,
                         cudaFuncAttributeMaxDynamicSharedMemorySize, GEMM_SMEM);

    int4* rank4;
    cudaGetSymbolAddress((void**)&rank4, g_rank);

    conv_hist_kernel<<<(N_NODES * 8 + 255) / 256, 256>>>(
        feat4, (const int4*)edst, rank4);
    scan_kernel<<<SCAN_BLOCKS, 256>>>();
    fill_kernel<<<(N_EDGES / 4 + 255) / 256, 256>>>(
        (const int4*)esrc, (const int4*)edst, (const float4*)ew,
        (const int4*)rank4);
    gather_kernel<<<(N_NODES * 8 + 255) / 256, 256>>>();
    gemm_norm_kernel<<<N_TILES, 256, GEMM_SMEM>>>(feat4, W, bias, out4);

    (void)in_sizes; (void)n_in; (void)out_size;
}